// round 2
// baseline (speedup 1.0000x reference)
#include <cuda_runtime.h>
#include <cuda_bf16.h>
#include <math.h>

// ---------------- problem constants ----------------
#define NTOK   512
#define DDIM   768
#define MDIM   3072
#define NGRP   4
#define NEXP   8          // experts per group
#define NE_ALL 32         // total experts
#define NASSIGN 2048      // NTOK * KG * KE (always exact)
#define MAXCHUNK 64       // rows per GEMM chunk
#define MAXCHUNKS 64      // sum ceil(cnt/64) <= 63

// ---------------- scratch (device globals; no allocation) ----------------
__device__ float g_xg[NASSIGN * DDIM];            // gathered x, expert-sorted   (6.3 MB)
__device__ float g_h [NASSIGN * MDIM];            // gelu(fc1) per assignment    (25.2 MB)
__device__ float g_y [NASSIGN * DDIM];            // fc2 output per assignment   (6.3 MB)
__device__ int   g_assign_expert[NASSIGN];
__device__ float g_assign_w[NASSIGN];
__device__ int   g_pos[NASSIGN];                  // assignment -> sorted position
__device__ int   g_sorted[NASSIGN];               // sorted position -> assignment
__device__ int   g_chunks[MAXCHUNKS * 3];         // (expert, row0, len)
__device__ int   g_nchunks;

// ---------------- f32x2 packed helpers (PTX-only on sm_103a) ----------------
typedef unsigned long long ull;

__device__ __forceinline__ ull pk2(float lo, float hi) {
    ull r;
    asm("mov.b64 %0, {%1, %2};" : "=l"(r) : "f"(lo), "f"(hi));
    return r;
}
__device__ __forceinline__ void upk2(ull v, float& lo, float& hi) {
    asm("mov.b64 {%0, %1}, %2;" : "=f"(lo), "=f"(hi) : "l"(v));
}
__device__ __forceinline__ void fma2(ull& d, ull a, ull b) {
    asm("fma.rn.f32x2 %0, %1, %2, %0;" : "+l"(d) : "l"(a), "l"(b));
}

__device__ __forceinline__ float gelu_exact(float v) {
    return 0.5f * v * (1.0f + erff(v * 0.70710678118654752440f));
}

// ---------------- K1: routing (one warp per token) ----------------
__global__ void routing_kernel(const float* __restrict__ x,
                               const float* __restrict__ Wg,
                               const float* __restrict__ bg,
                               const float* __restrict__ Wge,
                               const float* __restrict__ bge) {
    int warp = threadIdx.x >> 5;
    int lane = threadIdx.x & 31;
    int n = blockIdx.x * 8 + warp;
    if (n >= NTOK) return;
    const float* xr = x + (size_t)n * DDIM;

    // group logits
    float ga[NGRP] = {0.f, 0.f, 0.f, 0.f};
    for (int d = lane; d < DDIM; d += 32) {
        float xv = xr[d];
        float4 wv = *reinterpret_cast<const float4*>(Wg + (size_t)d * NGRP);
        ga[0] += xv * wv.x; ga[1] += xv * wv.y;
        ga[2] += xv * wv.z; ga[3] += xv * wv.w;
    }
#pragma unroll
    for (int g = 0; g < NGRP; g++) {
#pragma unroll
        for (int o = 16; o; o >>= 1) ga[g] += __shfl_xor_sync(0xFFFFFFFFu, ga[g], o);
        ga[g] += bg[g];
    }
    // top-2 groups (stable: earliest index wins ties, matching jax top_k)
    int g0 = 0;
    for (int g = 1; g < NGRP; g++) if (ga[g] > ga[g0]) g0 = g;
    int g1 = -1; float best = -INFINITY;
    for (int g = 0; g < NGRP; g++) if (g != g0 && ga[g] > best) { best = ga[g]; g1 = g; }
    float t = expf(ga[g1] - ga[g0]);
    float gg0 = 1.0f / (1.0f + t);
    float gg1 = t * gg0;
    int   gs[2]  = {g0, g1};
    float ggs[2] = {gg0, gg1};

    for (int j = 0; j < 2; j++) {
        int g = gs[j];
        const float* Wb = Wge + (size_t)g * DDIM * NEXP;
        float ea[NEXP];
#pragma unroll
        for (int e = 0; e < NEXP; e++) ea[e] = 0.f;
        for (int d = lane; d < DDIM; d += 32) {
            float xv = xr[d];
            float4 w0 = *reinterpret_cast<const float4*>(Wb + (size_t)d * NEXP);
            float4 w1 = *reinterpret_cast<const float4*>(Wb + (size_t)d * NEXP + 4);
            ea[0] += xv * w0.x; ea[1] += xv * w0.y; ea[2] += xv * w0.z; ea[3] += xv * w0.w;
            ea[4] += xv * w1.x; ea[5] += xv * w1.y; ea[6] += xv * w1.z; ea[7] += xv * w1.w;
        }
#pragma unroll
        for (int e = 0; e < NEXP; e++) {
#pragma unroll
            for (int o = 16; o; o >>= 1) ea[e] += __shfl_xor_sync(0xFFFFFFFFu, ea[e], o);
            ea[e] += bge[g * NEXP + e];
        }
        int e0 = 0;
        for (int e = 1; e < NEXP; e++) if (ea[e] > ea[e0]) e0 = e;
        int e1 = -1; float b2v = -INFINITY;
        for (int e = 0; e < NEXP; e++) if (e != e0 && ea[e] > b2v) { b2v = ea[e]; e1 = e; }
        float te  = expf(ea[e1] - ea[e0]);
        float eg0 = 1.0f / (1.0f + te);
        float eg1 = te * eg0;
        if (lane == 0) {
            int a0 = n * 4 + j * 2;
            g_assign_expert[a0]     = g * NEXP + e0;
            g_assign_w[a0]          = ggs[j] * eg0;
            g_assign_expert[a0 + 1] = g * NEXP + e1;
            g_assign_w[a0 + 1]      = ggs[j] * eg1;
        }
    }
}

// ---------------- K2: counting sort by expert + chunk worklist ----------------
__global__ void sort_kernel() {
    __shared__ int sc[NE_ALL];
    __shared__ int scur[NE_ALL];
    int tid = threadIdx.x;
    if (tid < NE_ALL) sc[tid] = 0;
    __syncthreads();
    for (int a = tid; a < NASSIGN; a += blockDim.x)
        atomicAdd(&sc[g_assign_expert[a]], 1);
    __syncthreads();
    if (tid == 0) {
        int off = 0, nc = 0;
        for (int e = 0; e < NE_ALL; e++) {
            scur[e] = off;
            int c = sc[e], st = off, o2 = 0;
            while (o2 < c) {
                int len = min(MAXCHUNK, c - o2);
                g_chunks[nc * 3 + 0] = e;
                g_chunks[nc * 3 + 1] = st + o2;
                g_chunks[nc * 3 + 2] = len;
                nc++; o2 += MAXCHUNK;
            }
            off += c;
        }
        g_nchunks = nc;
    }
    __syncthreads();
    for (int a = tid; a < NASSIGN; a += blockDim.x) {
        int e = g_assign_expert[a];
        int p = atomicAdd(&scur[e], 1);
        g_pos[a] = p;
        g_sorted[p] = a;
    }
}

// ---------------- K3: gather x rows into sorted order ----------------
__global__ void gather_kernel(const float* __restrict__ x) {
    int p = blockIdx.x;
    int a = g_sorted[p];
    int n = a >> 2;
    const float4* src = reinterpret_cast<const float4*>(x + (size_t)n * DDIM);
    float4* dst = reinterpret_cast<float4*>(g_xg + (size_t)p * DDIM);
    dst[threadIdx.x] = src[threadIdx.x];  // 192 threads * float4 = 768 floats
}

// ---------------- K4/K5: expert GEMM (BM=64, BN=128, BK=16, f32x2 math) ----
// FC1: C = gelu(A[64,768] @ W1[e][768,3072-tile] + b1)   A=g_xg, C=g_h
// FC2: C =       A[64,3072] @ W2[e][3072,768-tile] + b2  A=g_h,  C=g_y
template <bool FC1>
__global__ void __launch_bounds__(256) expert_gemm(const float* __restrict__ Wt,
                                                   const float* __restrict__ bias) {
    int chunk = blockIdx.y;
    if (chunk >= g_nchunks) return;
    int e    = g_chunks[chunk * 3 + 0];
    int row0 = g_chunks[chunk * 3 + 1];
    int len  = g_chunks[chunk * 3 + 2];

    const int K   = FC1 ? DDIM : MDIM;
    const int LDA = FC1 ? DDIM : MDIM;
    const int N   = FC1 ? MDIM : DDIM;
    const float* A = (FC1 ? g_xg : g_h) + (size_t)row0 * LDA;
    float*       C = (FC1 ? g_h  : g_y) + (size_t)row0 * N + blockIdx.x * 128;
    const float* B = Wt   + (size_t)e * K * N + blockIdx.x * 128;
    const float* brow = bias + (size_t)e * N + blockIdx.x * 128;

    __shared__ float Xs[2][16][64];
    __shared__ float Ws[2][16][128];

    int tid = threadIdx.x;
    int tx  = tid & 31;          // col group: cols tx*4 .. tx*4+3
    int ty  = tid >> 5;          // row group: rows ty*8 .. ty*8+7
    int ar  = tid >> 2;          // A-load row 0..63
    int ak  = (tid & 3) * 4;     // A-load k offset
    int bkr = tid >> 5;          // B-load k row (and +8)
    int bc  = (tid & 31) * 4;    // B-load col

    ull acc[4][4];
#pragma unroll
    for (int i = 0; i < 4; i++)
#pragma unroll
        for (int j = 0; j < 4; j++) acc[i][j] = 0ull;

    const int nk = K / 16;

    // prologue: tile 0
    float4 aR = (ar < len) ? *reinterpret_cast<const float4*>(A + (size_t)ar * LDA + ak)
                           : make_float4(0.f, 0.f, 0.f, 0.f);
    float4 bR0 = *reinterpret_cast<const float4*>(B + (size_t)bkr * N + bc);
    float4 bR1 = *reinterpret_cast<const float4*>(B + (size_t)(bkr + 8) * N + bc);
    Xs[0][ak + 0][ar] = aR.x; Xs[0][ak + 1][ar] = aR.y;
    Xs[0][ak + 2][ar] = aR.z; Xs[0][ak + 3][ar] = aR.w;
    *reinterpret_cast<float4*>(&Ws[0][bkr][bc])     = bR0;
    *reinterpret_cast<float4*>(&Ws[0][bkr + 8][bc]) = bR1;
    __syncthreads();

    for (int t = 0; t < nk; t++) {
        int cur = t & 1;
        if (t + 1 < nk) {
            const float* An = A + (t + 1) * 16;
            const float* Bn = B + (size_t)(t + 1) * 16 * N;
            aR = (ar < len) ? *reinterpret_cast<const float4*>(An + (size_t)ar * LDA + ak)
                            : make_float4(0.f, 0.f, 0.f, 0.f);
            bR0 = *reinterpret_cast<const float4*>(Bn + (size_t)bkr * N + bc);
            bR1 = *reinterpret_cast<const float4*>(Bn + (size_t)(bkr + 8) * N + bc);
        }
#pragma unroll
        for (int k = 0; k < 16; k++) {
            const ull* ap = reinterpret_cast<const ull*>(&Xs[cur][k][ty * 8]);
            ull a01 = ap[0], a23 = ap[1], a45 = ap[2], a67 = ap[3];
            float4 bv = *reinterpret_cast<const float4*>(&Ws[cur][k][tx * 4]);
            ull bd0 = pk2(bv.x, bv.x), bd1 = pk2(bv.y, bv.y);
            ull bd2 = pk2(bv.z, bv.z), bd3 = pk2(bv.w, bv.w);
            fma2(acc[0][0], a01, bd0); fma2(acc[0][1], a01, bd1);
            fma2(acc[0][2], a01, bd2); fma2(acc[0][3], a01, bd3);
            fma2(acc[1][0], a23, bd0); fma2(acc[1][1], a23, bd1);
            fma2(acc[1][2], a23, bd2); fma2(acc[1][3], a23, bd3);
            fma2(acc[2][0], a45, bd0); fma2(acc[2][1], a45, bd1);
            fma2(acc[2][2], a45, bd2); fma2(acc[2][3], a45, bd3);
            fma2(acc[3][0], a67, bd0); fma2(acc[3][1], a67, bd1);
            fma2(acc[3][2], a67, bd2); fma2(acc[3][3], a67, bd3);
        }
        if (t + 1 < nk) {
            int nxt = cur ^ 1;
            Xs[nxt][ak + 0][ar] = aR.x; Xs[nxt][ak + 1][ar] = aR.y;
            Xs[nxt][ak + 2][ar] = aR.z; Xs[nxt][ak + 3][ar] = aR.w;
            *reinterpret_cast<float4*>(&Ws[nxt][bkr][bc])     = bR0;
            *reinterpret_cast<float4*>(&Ws[nxt][bkr + 8][bc]) = bR1;
        }
        __syncthreads();
    }

    // epilogue
    float4 bb = *reinterpret_cast<const float4*>(brow + tx * 4);
#pragma unroll
    for (int ip = 0; ip < 4; ip++) {
        float lo[4], hi[4];
#pragma unroll
        for (int j = 0; j < 4; j++) upk2(acc[ip][j], lo[j], hi[j]);
        int m0 = ty * 8 + ip * 2;
        if (m0 < len) {
            float4 o;
            o.x = lo[0] + bb.x; o.y = lo[1] + bb.y;
            o.z = lo[2] + bb.z; o.w = lo[3] + bb.w;
            if (FC1) { o.x = gelu_exact(o.x); o.y = gelu_exact(o.y);
                       o.z = gelu_exact(o.z); o.w = gelu_exact(o.w); }
            *reinterpret_cast<float4*>(C + (size_t)m0 * N + tx * 4) = o;
        }
        if (m0 + 1 < len) {
            float4 o;
            o.x = hi[0] + bb.x; o.y = hi[1] + bb.y;
            o.z = hi[2] + bb.z; o.w = hi[3] + bb.w;
            if (FC1) { o.x = gelu_exact(o.x); o.y = gelu_exact(o.y);
                       o.z = gelu_exact(o.z); o.w = gelu_exact(o.w); }
            *reinterpret_cast<float4*>(C + (size_t)(m0 + 1) * N + tx * 4) = o;
        }
    }
}

// ---------------- K6: weighted combine ----------------
__global__ void combine_kernel(float* __restrict__ out) {
    int n = blockIdx.x;
    float w[4]; int p[4];
#pragma unroll
    for (int s = 0; s < 4; s++) {
        w[s] = g_assign_w[n * 4 + s];
        p[s] = g_pos[n * 4 + s];
    }
    int d = threadIdx.x * 4;
    float4 r = make_float4(0.f, 0.f, 0.f, 0.f);
#pragma unroll
    for (int s = 0; s < 4; s++) {
        float4 v = *reinterpret_cast<const float4*>(g_y + (size_t)p[s] * DDIM + d);
        r.x += w[s] * v.x; r.y += w[s] * v.y;
        r.z += w[s] * v.z; r.w += w[s] * v.w;
    }
    *reinterpret_cast<float4*>(out + (size_t)n * DDIM + d) = r;
}

// ---------------- launch ----------------
extern "C" void kernel_launch(void* const* d_in, const int* in_sizes, int n_in,
                              void* d_out, int out_size) {
    const float* x   = (const float*)d_in[0];
    const float* Wg  = (const float*)d_in[1];
    const float* bg  = (const float*)d_in[2];
    const float* Wge = (const float*)d_in[3];
    const float* bge = (const float*)d_in[4];
    const float* W1  = (const float*)d_in[5];
    const float* b1  = (const float*)d_in[6];
    const float* W2  = (const float*)d_in[7];
    const float* b2  = (const float*)d_in[8];
    float* out = (float*)d_out;

    routing_kernel<<<64, 256>>>(x, Wg, bg, Wge, bge);
    sort_kernel<<<1, 256>>>();
    gather_kernel<<<NASSIGN, 192>>>(x);
    expert_gemm<true ><<<dim3(MDIM / 128, MAXCHUNKS), 256>>>(W1, b1);
    expert_gemm<false><<<dim3(DDIM / 128, MAXCHUNKS), 256>>>(W2, b2);
    combine_kernel<<<NTOK, 192>>>(out);
}

// round 5
// speedup vs baseline: 2.5961x; 2.5961x over previous
#include <cuda_runtime.h>
#include <cuda_bf16.h>
#include <math.h>
#include <stdint.h>

// ---------------- problem constants ----------------
#define NTOK   512
#define DDIM   768
#define MDIM   3072
#define NGRP   4
#define NEXP   8
#define NE_ALL 32
#define NASSIGN 2048      // NTOK * KG * KE
#define MAXCHUNK 64       // rows per GEMM chunk (M tile)
#define MAXCHUNKS 64      // sum ceil(cnt/64) <= 64

// ---------------- scratch (device globals; no allocation) ----------------
__device__ float g_xg[NASSIGN * DDIM];            // gathered x (tf32-rounded)
__device__ float g_h [NASSIGN * MDIM];            // gelu(fc1)  (tf32-rounded)
__device__ float g_y [NASSIGN * DDIM];            // fc2 output (fp32)
__device__ int   g_assign_expert[NASSIGN];
__device__ float g_assign_w[NASSIGN];
__device__ int   g_pos[NASSIGN];
__device__ int   g_sorted[NASSIGN];
__device__ int   g_chunks[MAXCHUNKS * 3];         // (expert, row0, len)
__device__ int   g_nchunks;

// ---------------- PTX helpers (sm_80-compatible only) ----------------
__device__ __forceinline__ uint32_t smem_u32(const void* p) {
    uint32_t a;
    asm("{ .reg .u64 t; cvta.to.shared.u64 t, %1; cvt.u32.u64 %0, t; }" : "=r"(a) : "l"(p));
    return a;
}
__device__ __forceinline__ uint32_t tf32rn(float f) {
    uint32_t r;
    asm("cvt.rna.tf32.f32 %0, %1;" : "=r"(r) : "f"(f));
    return r;
}
__device__ __forceinline__ void mma_tf32(float* c, const uint32_t* a, uint32_t b0, uint32_t b1) {
    asm volatile("mma.sync.aligned.m16n8k8.row.col.f32.tf32.tf32.f32 "
                 "{%0,%1,%2,%3}, {%4,%5,%6,%7}, {%8,%9}, {%0,%1,%2,%3};"
                 : "+f"(c[0]), "+f"(c[1]), "+f"(c[2]), "+f"(c[3])
                 : "r"(a[0]), "r"(a[1]), "r"(a[2]), "r"(a[3]), "r"(b0), "r"(b1));
}
#define CP_ASYNC16(dst, src) \
    asm volatile("cp.async.cg.shared.global [%0], [%1], 16;" :: "r"(dst), "l"(src))
#define CP_COMMIT() asm volatile("cp.async.commit_group;" ::: "memory")
#define CP_WAIT2()  asm volatile("cp.async.wait_group 2;"  ::: "memory")

__device__ __forceinline__ float gelu_exact(float v) {
    return 0.5f * v * (1.0f + erff(v * 0.70710678118654752440f));
}

// ---------------- K1: routing (one warp per token, fp32) ----------------
__global__ void routing_kernel(const float* __restrict__ x,
                               const float* __restrict__ Wg,
                               const float* __restrict__ bg,
                               const float* __restrict__ Wge,
                               const float* __restrict__ bge) {
    int warp = threadIdx.x >> 5;
    int lane = threadIdx.x & 31;
    int n = blockIdx.x * 8 + warp;
    if (n >= NTOK) return;
    const float* xr = x + (size_t)n * DDIM;

    float ga[NGRP] = {0.f, 0.f, 0.f, 0.f};
    for (int d = lane; d < DDIM; d += 32) {
        float xv = xr[d];
        float4 wv = *reinterpret_cast<const float4*>(Wg + (size_t)d * NGRP);
        ga[0] += xv * wv.x; ga[1] += xv * wv.y;
        ga[2] += xv * wv.z; ga[3] += xv * wv.w;
    }
#pragma unroll
    for (int g = 0; g < NGRP; g++) {
#pragma unroll
        for (int o = 16; o; o >>= 1) ga[g] += __shfl_xor_sync(0xFFFFFFFFu, ga[g], o);
        ga[g] += bg[g];
    }
    int g0 = 0;
    for (int g = 1; g < NGRP; g++) if (ga[g] > ga[g0]) g0 = g;
    int g1 = -1; float best = -INFINITY;
    for (int g = 0; g < NGRP; g++) if (g != g0 && ga[g] > best) { best = ga[g]; g1 = g; }
    float t = expf(ga[g1] - ga[g0]);
    float gg0 = 1.0f / (1.0f + t);
    float gg1 = t * gg0;
    int   gs[2]  = {g0, g1};
    float ggs[2] = {gg0, gg1};

    for (int j = 0; j < 2; j++) {
        int g = gs[j];
        const float* Wb = Wge + (size_t)g * DDIM * NEXP;
        float ea[NEXP];
#pragma unroll
        for (int e = 0; e < NEXP; e++) ea[e] = 0.f;
        for (int d = lane; d < DDIM; d += 32) {
            float xv = xr[d];
            float4 w0 = *reinterpret_cast<const float4*>(Wb + (size_t)d * NEXP);
            float4 w1 = *reinterpret_cast<const float4*>(Wb + (size_t)d * NEXP + 4);
            ea[0] += xv * w0.x; ea[1] += xv * w0.y; ea[2] += xv * w0.z; ea[3] += xv * w0.w;
            ea[4] += xv * w1.x; ea[5] += xv * w1.y; ea[6] += xv * w1.z; ea[7] += xv * w1.w;
        }
#pragma unroll
        for (int e = 0; e < NEXP; e++) {
#pragma unroll
            for (int o = 16; o; o >>= 1) ea[e] += __shfl_xor_sync(0xFFFFFFFFu, ea[e], o);
            ea[e] += bge[g * NEXP + e];
        }
        int e0 = 0;
        for (int e = 1; e < NEXP; e++) if (ea[e] > ea[e0]) e0 = e;
        int e1 = -1; float b2v = -INFINITY;
        for (int e = 0; e < NEXP; e++) if (e != e0 && ea[e] > b2v) { b2v = ea[e]; e1 = e; }
        float te  = expf(ea[e1] - ea[e0]);
        float eg0 = 1.0f / (1.0f + te);
        float eg1 = te * eg0;
        if (lane == 0) {
            int a0 = n * 4 + j * 2;
            g_assign_expert[a0]     = g * NEXP + e0;
            g_assign_w[a0]          = ggs[j] * eg0;
            g_assign_expert[a0 + 1] = g * NEXP + e1;
            g_assign_w[a0 + 1]      = ggs[j] * eg1;
        }
    }
}

// ---------------- K2: counting sort + chunk worklist ----------------
__global__ void sort_kernel() {
    __shared__ int sc[NE_ALL];
    __shared__ int scur[NE_ALL];
    int tid = threadIdx.x;
    if (tid < NE_ALL) sc[tid] = 0;
    __syncthreads();
    for (int a = tid; a < NASSIGN; a += blockDim.x)
        atomicAdd(&sc[g_assign_expert[a]], 1);
    __syncthreads();
    if (tid == 0) {
        int off = 0, nc = 0;
        for (int e = 0; e < NE_ALL; e++) {
            scur[e] = off;
            int c = sc[e], st = off, o2 = 0;
            while (o2 < c) {
                int len = min(MAXCHUNK, c - o2);
                g_chunks[nc * 3 + 0] = e;
                g_chunks[nc * 3 + 1] = st + o2;
                g_chunks[nc * 3 + 2] = len;
                nc++; o2 += MAXCHUNK;
            }
            off += c;
        }
        g_nchunks = nc;
    }
    __syncthreads();
    for (int a = tid; a < NASSIGN; a += blockDim.x) {
        int e = g_assign_expert[a];
        int p = atomicAdd(&scur[e], 1);
        g_pos[a] = p;
        g_sorted[p] = a;
    }
}

// ---------------- K3: gather x rows (tf32 RN pre-round) ----------------
__global__ void gather_kernel(const float* __restrict__ x) {
    int p = blockIdx.x;
    int a = g_sorted[p];
    int n = a >> 2;
    const float4* src = reinterpret_cast<const float4*>(x + (size_t)n * DDIM);
    float4 v = src[threadIdx.x];
    v.x = __uint_as_float(tf32rn(v.x));
    v.y = __uint_as_float(tf32rn(v.y));
    v.z = __uint_as_float(tf32rn(v.z));
    v.w = __uint_as_float(tf32rn(v.w));
    reinterpret_cast<float4*>(g_xg + (size_t)p * DDIM)[threadIdx.x] = v;
}

// ---------------- K4/K5: mma.sync tf32 expert GEMM ----------------
// CTA tile 64x256x32, 8 warps (2 M x 4 N), warp tile 32x64, 4-stage cp.async.
template <bool FC1>
__global__ void __launch_bounds__(256, 1) moe_gemm_mma(const float* __restrict__ W,
                                                       const float* __restrict__ bias) {
    constexpr int K    = FC1 ? DDIM : MDIM;   // 768 / 3072
    constexpr int NF   = FC1 ? MDIM : DDIM;   // 3072 / 768
    constexpr int BM   = 64, BN = 256, BK = 32;
    constexpr int NKI  = K / BK;
    constexpr int S    = 4;                   // pipeline stages
    constexpr int APAD = 36;                  // floats per A row
    constexpr int BPAD = 264;                 // floats per B row
    constexpr int AFL  = BM * APAD;           // floats per A stage
    constexpr int BFL  = BK * BPAD;           // floats per B stage
    constexpr int ABYTES = AFL * 4;
    constexpr int BBYTES = BFL * 4;

    int chunk = blockIdx.y;
    if (chunk >= g_nchunks) return;
    const int e    = g_chunks[chunk * 3 + 0];
    const int row0 = g_chunks[chunk * 3 + 1];
    const int len  = g_chunks[chunk * 3 + 2];
    const int n0   = blockIdx.x * BN;

    extern __shared__ float dsm[];
    float* aS = dsm;             // S stages, AFL floats each
    float* bS = dsm + S * AFL;   // S stages, BFL floats each
    __shared__ float s_bias[BN];

    const uint32_t a_u32 = smem_u32(aS);
    const uint32_t b_u32 = smem_u32(bS);

    const int tid = threadIdx.x;
    const int wid = tid >> 5, lane = tid & 31;
    const int gid = lane >> 2, tig = lane & 3;
    const int M0w = (wid >> 2) * 32;
    const int N0w = (wid & 3) * 64;

    const float* Aptr = (FC1 ? g_xg : g_h) + (size_t)row0 * K;
    float*       Cptr = (FC1 ? g_h  : g_y) + (size_t)row0 * NF + n0;
    const float* Bptr = W + (size_t)e * K * NF + n0;

    s_bias[tid] = bias[(size_t)e * NF + n0 + tid];  // blockDim==BN==256
    __syncthreads();

    // cp.async source/dest precomputation
    const int ar = tid >> 3, aq = tid & 7;     // A: row 0..31 (+32), 16B chunk 0..7
    const int bk = tid >> 5, bq = tid & 31;    // B: k 0..7 (+8,16,24), chunk pair

    auto load_tile = [&](int t) {
        const int s  = t & (S - 1);
        const int kb = t * BK;
#pragma unroll
        for (int j = 0; j < 2; j++) {
            int m  = ar + 32 * j;
            int mc = min(m, len - 1);           // clamp: stay in-bounds, rows >= len discarded
            const float* src = Aptr + (size_t)mc * K + kb + aq * 4;
            uint32_t dst = a_u32 + (uint32_t)(s * ABYTES + (m * APAD + aq * 4) * 4);
            CP_ASYNC16(dst, src);
        }
#pragma unroll
        for (int j = 0; j < 4; j++) {
            int k = bk + 8 * j;
            const float* srow = Bptr + (size_t)(kb + k) * NF;
            uint32_t drow = b_u32 + (uint32_t)(s * BBYTES + k * BPAD * 4);
            CP_ASYNC16(drow + bq * 16u,        srow + bq * 4);        // cols [0,128)
            CP_ASYNC16(drow + 512u + bq * 16u, srow + 128 + bq * 4);  // cols [128,256)
        }
    };

    float acc[2][8][4];
#pragma unroll
    for (int mt = 0; mt < 2; mt++)
#pragma unroll
        for (int nt = 0; nt < 8; nt++)
#pragma unroll
            for (int i = 0; i < 4; i++) acc[mt][nt][i] = 0.f;

    // prologue: S-1 tiles in flight
    load_tile(0); CP_COMMIT();
    load_tile(1); CP_COMMIT();
    load_tile(2); CP_COMMIT();

    for (int t = 0; t < NKI; t++) {
        CP_WAIT2();
        __syncthreads();
        if (t + S - 1 < NKI) load_tile(t + S - 1);
        CP_COMMIT();

        const int s = t & (S - 1);
        const float* As = aS + s * AFL;
        const float* Bs = bS + s * BFL;
#pragma unroll
        for (int kk = 0; kk < 4; kk++) {
            const int k0 = kk * 8;
            uint32_t a[2][4];
#pragma unroll
            for (int mt = 0; mt < 2; mt++) {
                const float* p = As + (M0w + mt * 16 + gid) * APAD + k0 + tig;
                a[mt][0] = __float_as_uint(p[0]);
                a[mt][1] = __float_as_uint(p[8 * APAD]);
                a[mt][2] = __float_as_uint(p[4]);
                a[mt][3] = __float_as_uint(p[8 * APAD + 4]);
            }
#pragma unroll
            for (int nt = 0; nt < 8; nt++) {
                const float* p = Bs + (size_t)(k0 + tig) * BPAD + N0w + nt * 8 + gid;
                uint32_t b0 = tf32rn(p[0]);
                uint32_t b1 = tf32rn(p[4 * BPAD]);
                mma_tf32(acc[0][nt], a[0], b0, b1);
                mma_tf32(acc[1][nt], a[1], b0, b1);
            }
        }
    }

    // epilogue: bias (+gelu, +tf32 round for fc1), guarded by len
#pragma unroll
    for (int mt = 0; mt < 2; mt++) {
#pragma unroll
        for (int rr = 0; rr < 2; rr++) {
            int row = M0w + mt * 16 + gid + 8 * rr;
            if (row < len) {
                float* Crow = Cptr + (size_t)row * NF;
#pragma unroll
                for (int nt = 0; nt < 8; nt++) {
                    int col = N0w + nt * 8 + tig * 2;
                    float v0 = acc[mt][nt][2 * rr + 0] + s_bias[col];
                    float v1 = acc[mt][nt][2 * rr + 1] + s_bias[col + 1];
                    if (FC1) {
                        v0 = __uint_as_float(tf32rn(gelu_exact(v0)));
                        v1 = __uint_as_float(tf32rn(gelu_exact(v1)));
                    }
                    *reinterpret_cast<float2*>(Crow + col) = make_float2(v0, v1);
                }
            }
        }
    }
}

// ---------------- K6: weighted combine ----------------
__global__ void combine_kernel(float* __restrict__ out) {
    int n = blockIdx.x;
    float w[4]; int p[4];
#pragma unroll
    for (int s = 0; s < 4; s++) {
        w[s] = g_assign_w[n * 4 + s];
        p[s] = g_pos[n * 4 + s];
    }
    int d = threadIdx.x * 4;
    float4 r = make_float4(0.f, 0.f, 0.f, 0.f);
#pragma unroll
    for (int s = 0; s < 4; s++) {
        float4 v = *reinterpret_cast<const float4*>(g_y + (size_t)p[s] * DDIM + d);
        r.x += w[s] * v.x; r.y += w[s] * v.y;
        r.z += w[s] * v.z; r.w += w[s] * v.w;
    }
    *reinterpret_cast<float4*>(out + (size_t)n * DDIM + d) = r;
}

// ---------------- launch ----------------
extern "C" void kernel_launch(void* const* d_in, const int* in_sizes, int n_in,
                              void* d_out, int out_size) {
    const float* x   = (const float*)d_in[0];
    const float* Wg  = (const float*)d_in[1];
    const float* bg  = (const float*)d_in[2];
    const float* Wge = (const float*)d_in[3];
    const float* bge = (const float*)d_in[4];
    const float* W1  = (const float*)d_in[5];
    const float* b1  = (const float*)d_in[6];
    const float* W2  = (const float*)d_in[7];
    const float* b2  = (const float*)d_in[8];
    float* out = (float*)d_out;

    // dynamic smem: 4 stages * (64*36 + 32*264) floats = 172032 bytes
    const int dyn = 4 * (64 * 36 + 32 * 264) * 4;
    cudaFuncSetAttribute(moe_gemm_mma<true>,  cudaFuncAttributeMaxDynamicSharedMemorySize, dyn);
    cudaFuncSetAttribute(moe_gemm_mma<false>, cudaFuncAttributeMaxDynamicSharedMemorySize, dyn);

    routing_kernel<<<64, 256>>>(x, Wg, bg, Wge, bge);
    sort_kernel<<<1, 256>>>();
    gather_kernel<<<NASSIGN, 192>>>(x);
    moe_gemm_mma<true ><<<dim3(MDIM / 256, MAXCHUNKS), 256, dyn>>>(W1, b1);
    moe_gemm_mma<false><<<dim3(DDIM / 256, MAXCHUNKS), 256, dyn>>>(W2, b2);
    combine_kernel<<<NTOK, 192>>>(out);
}